// round 1
// baseline (speedup 1.0000x reference)
#include <cuda_runtime.h>
#include <cuda_bf16.h>

#define N_NODES 100000
#define N_EDGES 1200000
#define D 64
#define RW 3
#define OUT_COLS 384  // 2 * (L+1) * D

// Scratch: h[node][window][64], agg[node][window][64]
__device__ float g_h  [(size_t)N_NODES * RW * D];
__device__ float g_agg[(size_t)N_NODES * RW * D];

// Warp-level LayerNorm over 64 floats held as float2 per lane (biased var, eps 1e-5)
__device__ __forceinline__ float2 warp_ln(float2 v) {
    float s  = v.x + v.y;
    float ss = v.x * v.x + v.y * v.y;
    #pragma unroll
    for (int o = 16; o; o >>= 1) {
        s  += __shfl_xor_sync(0xFFFFFFFFu, s,  o);
        ss += __shfl_xor_sync(0xFFFFFFFFu, ss, o);
    }
    const float inv_d = 1.0f / (float)D;
    float mu  = s * inv_d;
    float var = ss * inv_d - mu * mu;
    float r   = rsqrtf(var + 1e-5f);
    return make_float2((v.x - mu) * r, (v.y - mu) * r);
}

// Kernel 1: hn = LN(feature); seed 3 masked windows; write layer-0 output blocks.
__global__ __launch_bounds__(256) void init_kernel(
    const float* __restrict__ feat, const int* __restrict__ age,
    float* __restrict__ out)
{
    int warp = (blockIdx.x * blockDim.x + threadIdx.x) >> 5;
    int lane = threadIdx.x & 31;
    if (warp >= N_NODES) return;

    float2 v = reinterpret_cast<const float2*>(feat + (size_t)warp * D)[lane];
    float2 hn = warp_ln(v);

    int a = age[warp];
    float m1 = (a >= 1) ? 1.0f : 0.0f;
    float m2 = (a >= 2) ? 1.0f : 0.0f;

    float* hb = g_h + (size_t)warp * (RW * D);
    reinterpret_cast<float2*>(hb         )[lane] = hn;
    reinterpret_cast<float2*>(hb +     D )[lane] = make_float2(hn.x * m1, hn.y * m1);
    reinterpret_cast<float2*>(hb + 2 * D )[lane] = make_float2(hn.x * m2, hn.y * m2);

    float* ob = out + (size_t)warp * OUT_COLS;
    reinterpret_cast<float2*>(ob)[lane] = hn;                    // window0, layer0: cols [0,64)
    float tf = 1.0f - 0.5f * (m1 + m2);                          // temp layer0: cols [192,256)
    reinterpret_cast<float2*>(ob + 192)[lane] = make_float2(hn.x * tf, hn.y * tf);
}

// Kernel 2: edge scatter-add, warp per edge, all 3 windows, vector f32 reds.
__global__ __launch_bounds__(256) void agg_kernel(
    const int* __restrict__ src, const int* __restrict__ dst)
{
    int e    = (blockIdx.x * blockDim.x + threadIdx.x) >> 5;
    int lane = threadIdx.x & 31;
    if (e >= N_EDGES) return;

    int s = __ldg(src + e);
    int d = __ldg(dst + e);
    const float2* hs = reinterpret_cast<const float2*>(g_h + (size_t)s * (RW * D));
    float* ad = g_agg + (size_t)d * (RW * D);

    #pragma unroll
    for (int w = 0; w < RW; w++) {
        float2 v = hs[w * 32 + lane];
        float* p = ad + w * D + 2 * lane;
        asm volatile("red.global.add.v2.f32 [%0], {%1, %2};"
                     :: "l"(p), "f"(v.x), "f"(v.y) : "memory");
    }
}

// Kernel 3: per node, LN+ReLU each window's aggregate; zero agg for next round;
// write window0 + temporal blocks for this layer.
__global__ __launch_bounds__(256) void lnrelu_kernel(
    float* __restrict__ out, int layer)
{
    int warp = (blockIdx.x * blockDim.x + threadIdx.x) >> 5;
    int lane = threadIdx.x & 31;
    if (warp >= N_NODES) return;

    float* ab = g_agg + (size_t)warp * (RW * D);
    float* hb = g_h   + (size_t)warp * (RW * D);

    float2 r[RW];
    #pragma unroll
    for (int w = 0; w < RW; w++) {
        float2 v = reinterpret_cast<float2*>(ab + w * D)[lane];
        reinterpret_cast<float2*>(ab + w * D)[lane] = make_float2(0.f, 0.f);  // restore zeros
        float2 n = warp_ln(v);
        r[w] = make_float2(fmaxf(n.x, 0.f), fmaxf(n.y, 0.f));
        reinterpret_cast<float2*>(hb + w * D)[lane] = r[w];
    }

    float* ob = out + (size_t)warp * OUT_COLS + 64 * layer;
    reinterpret_cast<float2*>(ob)[lane] = r[0];
    float2 t = make_float2(r[0].x - 0.5f * (r[1].x + r[2].x),
                           r[0].y - 0.5f * (r[1].y + r[2].y));
    reinterpret_cast<float2*>(ob + 192)[lane] = t;
}

extern "C" void kernel_launch(void* const* d_in, const int* in_sizes, int n_in,
                              void* d_out, int out_size)
{
    const float* feat = (const float*)d_in[0];
    const int*   age  = (const int*)  d_in[1];
    const int*   src  = (const int*)  d_in[2];
    const int*   dst  = (const int*)  d_in[3];
    float* out = (float*)d_out;

    const int nodeBlocks = (N_NODES * 32 + 255) / 256;   // 12500
    const int edgeBlocks = (N_EDGES * 32 + 255) / 256;   // 150000

    init_kernel<<<nodeBlocks, 256>>>(feat, age, out);
    for (int l = 1; l <= 2; l++) {
        agg_kernel<<<edgeBlocks, 256>>>(src, dst);
        lnrelu_kernel<<<nodeBlocks, 256>>>(out, l);
    }
}

// round 2
// speedup vs baseline: 5.2917x; 5.2917x over previous
#include <cuda_runtime.h>
#include <cuda_bf16.h>

#define N_NODES 100000
#define N_EDGES 1200000
#define D 64
#define OUT_COLS 384
#define SCAN_BLK 512
#define NSCAN ((N_NODES + SCAN_BLK - 1) / SCAN_BLK)   // 196

// Scratch
__device__ float g_hn [(size_t)N_NODES * D];           // LN(feature)          25.6 MB
__device__ float g_h  [(size_t)N_NODES * 3 * D];       // layer-1 h, 3 windows 76.8 MB
__device__ int   g_deg   [N_NODES];
__device__ int   g_indptr[N_NODES + 1];
__device__ int   g_cursor[N_NODES];
__device__ int   g_csr   [N_EDGES];
__device__ int   g_blocksum[NSCAN];
__device__ int   g_blockoff[NSCAN];

// ---------- warp LayerNorm over 64 floats (float2 per lane), biased var, eps 1e-5 ----------
__device__ __forceinline__ float2 warp_ln(float2 v) {
    float s  = v.x + v.y;
    float ss = v.x * v.x + v.y * v.y;
    #pragma unroll
    for (int o = 16; o; o >>= 1) {
        s  += __shfl_xor_sync(0xFFFFFFFFu, s,  o);
        ss += __shfl_xor_sync(0xFFFFFFFFu, ss, o);
    }
    float mu  = s * (1.0f / D);
    float var = ss * (1.0f / D) - mu * mu;
    float r   = rsqrtf(var + 1e-5f);
    return make_float2((v.x - mu) * r, (v.y - mu) * r);
}
__device__ __forceinline__ float2 ln_relu(float2 v) {
    float2 n = warp_ln(v);
    return make_float2(fmaxf(n.x, 0.f), fmaxf(n.y, 0.f));
}

// ---------- init: hn = LN(feature); write layer-0 output blocks ----------
__global__ __launch_bounds__(256) void init_kernel(
    const float* __restrict__ feat, const int* __restrict__ age,
    float* __restrict__ out)
{
    int n    = (blockIdx.x * blockDim.x + threadIdx.x) >> 5;
    int lane = threadIdx.x & 31;
    if (n >= N_NODES) return;

    float2 v  = reinterpret_cast<const float2*>(feat + (size_t)n * D)[lane];
    float2 hn = warp_ln(v);
    reinterpret_cast<float2*>(g_hn + (size_t)n * D)[lane] = hn;

    int a = age[n];
    float tf = 1.0f - 0.5f * ((a >= 1 ? 1.f : 0.f) + (a >= 2 ? 1.f : 0.f));
    float* ob = out + (size_t)n * OUT_COLS;
    reinterpret_cast<float2*>(ob)[lane]       = hn;                                   // cols [0,64)
    reinterpret_cast<float2*>(ob + 192)[lane] = make_float2(hn.x * tf, hn.y * tf);    // cols [192,256)
}

// ---------- CSR build ----------
__global__ __launch_bounds__(256) void zero_deg_kernel() {
    int i = blockIdx.x * blockDim.x + threadIdx.x;
    if (i < N_NODES) g_deg[i] = 0;
}
__global__ __launch_bounds__(256) void hist_kernel(const int* __restrict__ dst) {
    int e = blockIdx.x * blockDim.x + threadIdx.x;
    if (e < N_EDGES) atomicAdd(&g_deg[dst[e]], 1);
}
__global__ __launch_bounds__(SCAN_BLK) void scanA_kernel() {   // per-block sums
    __shared__ int sd[SCAN_BLK];
    int i = blockIdx.x * SCAN_BLK + threadIdx.x;
    sd[threadIdx.x] = (i < N_NODES) ? g_deg[i] : 0;
    __syncthreads();
    #pragma unroll
    for (int o = SCAN_BLK / 2; o; o >>= 1) {
        if (threadIdx.x < o) sd[threadIdx.x] += sd[threadIdx.x + o];
        __syncthreads();
    }
    if (threadIdx.x == 0) g_blocksum[blockIdx.x] = sd[0];
}
__global__ void scanB_kernel() {                               // exclusive scan of block sums
    if (threadIdx.x == 0) {
        int acc = 0;
        for (int b = 0; b < NSCAN; b++) { g_blockoff[b] = acc; acc += g_blocksum[b]; }
    }
}
__global__ __launch_bounds__(SCAN_BLK) void scanC_kernel() {   // block-local exclusive scan + offset
    __shared__ int sd[SCAN_BLK];
    int i = blockIdx.x * SCAN_BLK + threadIdx.x;
    int v = (i < N_NODES) ? g_deg[i] : 0;
    sd[threadIdx.x] = v;
    __syncthreads();
    #pragma unroll
    for (int o = 1; o < SCAN_BLK; o <<= 1) {
        int t = (threadIdx.x >= o) ? sd[threadIdx.x - o] : 0;
        __syncthreads();
        sd[threadIdx.x] += t;
        __syncthreads();
    }
    if (i < N_NODES) {
        int excl = g_blockoff[blockIdx.x] + sd[threadIdx.x] - v;
        g_indptr[i] = excl;
        g_cursor[i] = excl;
        if (i == N_NODES - 1) g_indptr[N_NODES] = excl + v;
    }
}
__global__ __launch_bounds__(256) void scatter_kernel(
    const int* __restrict__ src, const int* __restrict__ dst)
{
    int e = blockIdx.x * blockDim.x + threadIdx.x;
    if (e >= N_EDGES) return;
    int pos = atomicAdd(&g_cursor[dst[e]], 1);
    g_csr[pos] = src[e];
}

// ---------- layer 1: gather hn + src-age masks -> 3 window sums -> LN+ReLU ----------
__global__ __launch_bounds__(256) void layer1_kernel(
    const int* __restrict__ age, float* __restrict__ out)
{
    int n    = (blockIdx.x * blockDim.x + threadIdx.x) >> 5;
    int lane = threadIdx.x & 31;
    if (n >= N_NODES) return;

    int beg = g_indptr[n], end = g_indptr[n + 1];
    float2 a0 = make_float2(0.f, 0.f), a1 = a0, a2 = a0;

    for (int base = beg; base < end; base += 32) {
        int cnt = min(32, end - base);
        int idx = (lane < cnt) ? g_csr[base + lane] : 0;
        int ag  = (lane < cnt) ? age[idx] : 0;
        for (int j = 0; j < cnt; j++) {
            int s  = __shfl_sync(0xFFFFFFFFu, idx, j);
            int sa = __shfl_sync(0xFFFFFFFFu, ag,  j);
            float2 v = reinterpret_cast<const float2*>(g_hn + (size_t)s * D)[lane];
            a0.x += v.x; a0.y += v.y;
            if (sa >= 1) { a1.x += v.x; a1.y += v.y; }
            if (sa >= 2) { a2.x += v.x; a2.y += v.y; }
        }
    }

    float2 r0 = ln_relu(a0), r1 = ln_relu(a1), r2 = ln_relu(a2);
    float* hb = g_h + (size_t)n * (3 * D);
    reinterpret_cast<float2*>(hb        )[lane] = r0;
    reinterpret_cast<float2*>(hb +     D)[lane] = r1;
    reinterpret_cast<float2*>(hb + 2 * D)[lane] = r2;

    float* ob = out + (size_t)n * OUT_COLS + 64;                 // layer-1 blocks
    reinterpret_cast<float2*>(ob)[lane] = r0;
    reinterpret_cast<float2*>(ob + 192)[lane] =
        make_float2(r0.x - 0.5f * (r1.x + r2.x), r0.y - 0.5f * (r1.y + r2.y));
}

// ---------- layer 2: gather 3-window h -> sums -> LN+ReLU -> final output blocks ----------
__global__ __launch_bounds__(256) void layer2_kernel(float* __restrict__ out)
{
    int n    = (blockIdx.x * blockDim.x + threadIdx.x) >> 5;
    int lane = threadIdx.x & 31;
    if (n >= N_NODES) return;

    int beg = g_indptr[n], end = g_indptr[n + 1];
    float2 a0 = make_float2(0.f, 0.f), a1 = a0, a2 = a0;

    for (int base = beg; base < end; base += 32) {
        int cnt = min(32, end - base);
        int idx = (lane < cnt) ? g_csr[base + lane] : 0;
        for (int j = 0; j < cnt; j++) {
            int s = __shfl_sync(0xFFFFFFFFu, idx, j);
            const float2* hs = reinterpret_cast<const float2*>(g_h + (size_t)s * (3 * D));
            float2 v0 = hs[lane];
            float2 v1 = hs[32 + lane];
            float2 v2 = hs[64 + lane];
            a0.x += v0.x; a0.y += v0.y;
            a1.x += v1.x; a1.y += v1.y;
            a2.x += v2.x; a2.y += v2.y;
        }
    }

    float2 r0 = ln_relu(a0), r1 = ln_relu(a1), r2 = ln_relu(a2);
    float* ob = out + (size_t)n * OUT_COLS + 128;                // layer-2 blocks
    reinterpret_cast<float2*>(ob)[lane] = r0;
    reinterpret_cast<float2*>(ob + 192)[lane] =
        make_float2(r0.x - 0.5f * (r1.x + r2.x), r0.y - 0.5f * (r1.y + r2.y));
}

extern "C" void kernel_launch(void* const* d_in, const int* in_sizes, int n_in,
                              void* d_out, int out_size)
{
    const float* feat = (const float*)d_in[0];
    const int*   age  = (const int*)  d_in[1];
    const int*   src  = (const int*)  d_in[2];
    const int*   dst  = (const int*)  d_in[3];
    float* out = (float*)d_out;

    const int nodeWarpBlocks = (N_NODES * 32 + 255) / 256;  // 12500
    const int nodeBlocks     = (N_NODES + 255) / 256;       // 391
    const int edgeBlocks     = (N_EDGES + 255) / 256;       // 4688

    init_kernel<<<nodeWarpBlocks, 256>>>(feat, age, out);
    zero_deg_kernel<<<nodeBlocks, 256>>>();
    hist_kernel<<<edgeBlocks, 256>>>(dst);
    scanA_kernel<<<NSCAN, SCAN_BLK>>>();
    scanB_kernel<<<1, 32>>>();
    scanC_kernel<<<NSCAN, SCAN_BLK>>>();
    scatter_kernel<<<edgeBlocks, 256>>>(src, dst);
    layer1_kernel<<<nodeWarpBlocks, 256>>>(age, out);
    layer2_kernel<<<nodeWarpBlocks, 256>>>(out);
}

// round 3
// speedup vs baseline: 6.2523x; 1.1815x over previous
#include <cuda_runtime.h>
#include <cuda_fp16.h>

#define N_NODES 100000
#define N_EDGES 1200000
#define D 64
#define OUT_COLS 384
#define SCAN_BLK 512
#define NSCAN ((N_NODES + SCAN_BLK - 1) / SCAN_BLK)   // 196
static_assert(NSCAN <= 256, "scanB assumes <=256 block sums");

// Scratch (fp16 feature tables to halve L2 gather traffic)
__device__ __half2 g_hn [(size_t)N_NODES * 32];        // LN(feature), 32 half2/node (12.8 MB)
__device__ __half2 g_h  [(size_t)N_NODES * 96];        // layer-1 h, [node][win3][32]   (38.4 MB)
__device__ int   g_deg   [N_NODES];
__device__ int   g_indptr[N_NODES + 1];
__device__ int   g_cursor[N_NODES];
__device__ int   g_csr   [N_EDGES];
__device__ int   g_blocksum[NSCAN];
__device__ int   g_blockoff[NSCAN];

// ---------- warp LayerNorm over 64 floats (float2 per lane), biased var, eps 1e-5 ----------
__device__ __forceinline__ float2 warp_ln(float2 v) {
    float s  = v.x + v.y;
    float ss = v.x * v.x + v.y * v.y;
    #pragma unroll
    for (int o = 16; o; o >>= 1) {
        s  += __shfl_xor_sync(0xFFFFFFFFu, s,  o);
        ss += __shfl_xor_sync(0xFFFFFFFFu, ss, o);
    }
    float mu  = s * (1.0f / D);
    float var = ss * (1.0f / D) - mu * mu;
    float r   = rsqrtf(var + 1e-5f);
    return make_float2((v.x - mu) * r, (v.y - mu) * r);
}
__device__ __forceinline__ float2 ln_relu(float2 v) {
    float2 n = warp_ln(v);
    return make_float2(fmaxf(n.x, 0.f), fmaxf(n.y, 0.f));
}
__device__ __forceinline__ void acc(float2& a, float2 v) { a.x += v.x; a.y += v.y; }

// ---------- init: hn = LN(feature) -> fp16 table; layer-0 output; zero deg ----------
__global__ __launch_bounds__(256) void init_kernel(
    const float* __restrict__ feat, const int* __restrict__ age,
    float* __restrict__ out)
{
    int n    = (blockIdx.x * blockDim.x + threadIdx.x) >> 5;
    int lane = threadIdx.x & 31;
    if (n >= N_NODES) return;

    float2 v  = reinterpret_cast<const float2*>(feat + (size_t)n * D)[lane];
    float2 hn = warp_ln(v);
    g_hn[(size_t)n * 32 + lane] = __float22half2_rn(hn);

    if (lane == 0) g_deg[n] = 0;

    int a = age[n];
    float tf = 1.0f - 0.5f * ((a >= 1 ? 1.f : 0.f) + (a >= 2 ? 1.f : 0.f));
    float* ob = out + (size_t)n * OUT_COLS;
    reinterpret_cast<float2*>(ob)[lane]       = hn;
    reinterpret_cast<float2*>(ob + 192)[lane] = make_float2(hn.x * tf, hn.y * tf);
}

// ---------- CSR build ----------
__global__ __launch_bounds__(256) void hist_kernel(const int* __restrict__ dst) {
    int e = blockIdx.x * blockDim.x + threadIdx.x;
    if (e < N_EDGES) atomicAdd(&g_deg[dst[e]], 1);
}
__global__ __launch_bounds__(SCAN_BLK) void scanA_kernel() {   // per-block sums
    __shared__ int sd[SCAN_BLK];
    int i = blockIdx.x * SCAN_BLK + threadIdx.x;
    sd[threadIdx.x] = (i < N_NODES) ? g_deg[i] : 0;
    __syncthreads();
    #pragma unroll
    for (int o = SCAN_BLK / 2; o; o >>= 1) {
        if (threadIdx.x < o) sd[threadIdx.x] += sd[threadIdx.x + o];
        __syncthreads();
    }
    if (threadIdx.x == 0) g_blocksum[blockIdx.x] = sd[0];
}
__global__ __launch_bounds__(256) void scanB_kernel() {        // parallel excl. scan of block sums
    __shared__ int sd[256];
    int t = threadIdx.x;
    int v = (t < NSCAN) ? g_blocksum[t] : 0;
    sd[t] = v;
    __syncthreads();
    #pragma unroll
    for (int o = 1; o < 256; o <<= 1) {
        int x = (t >= o) ? sd[t - o] : 0;
        __syncthreads();
        sd[t] += x;
        __syncthreads();
    }
    if (t < NSCAN) g_blockoff[t] = sd[t] - v;
}
__global__ __launch_bounds__(SCAN_BLK) void scanC_kernel() {   // block-local excl. scan + offset
    __shared__ int sd[SCAN_BLK];
    int i = blockIdx.x * SCAN_BLK + threadIdx.x;
    int v = (i < N_NODES) ? g_deg[i] : 0;
    sd[threadIdx.x] = v;
    __syncthreads();
    #pragma unroll
    for (int o = 1; o < SCAN_BLK; o <<= 1) {
        int t = (threadIdx.x >= o) ? sd[threadIdx.x - o] : 0;
        __syncthreads();
        sd[threadIdx.x] += t;
        __syncthreads();
    }
    if (i < N_NODES) {
        int excl = g_blockoff[blockIdx.x] + sd[threadIdx.x] - v;
        g_indptr[i] = excl;
        g_cursor[i] = excl;
        if (i == N_NODES - 1) g_indptr[N_NODES] = excl + v;
    }
}
__global__ __launch_bounds__(256) void scatter_kernel(
    const int* __restrict__ src, const int* __restrict__ dst)
{
    int e = blockIdx.x * blockDim.x + threadIdx.x;
    if (e >= N_EDGES) return;
    int pos = atomicAdd(&g_cursor[dst[e]], 1);
    g_csr[pos] = src[e];
}

// ---------- layer 1: gather hn(fp16) + src-age masks -> 3 window sums -> LN+ReLU ----------
__global__ __launch_bounds__(256) void layer1_kernel(
    const int* __restrict__ age, float* __restrict__ out)
{
    int n    = (blockIdx.x * blockDim.x + threadIdx.x) >> 5;
    int lane = threadIdx.x & 31;
    if (n >= N_NODES) return;

    int beg = g_indptr[n], end = g_indptr[n + 1];
    float2 a0 = make_float2(0.f, 0.f), a1 = a0, a2 = a0;

    for (int base = beg; base < end; base += 32) {
        int cnt = min(32, end - base);
        int idx = (lane < cnt) ? g_csr[base + lane] : 0;
        int ag  = (lane < cnt) ? __ldg(age + idx) : 0;
        int j = 0;
        for (; j + 4 <= cnt; j += 4) {
            int s0 = __shfl_sync(0xFFFFFFFFu, idx, j);
            int s1 = __shfl_sync(0xFFFFFFFFu, idx, j + 1);
            int s2 = __shfl_sync(0xFFFFFFFFu, idx, j + 2);
            int s3 = __shfl_sync(0xFFFFFFFFu, idx, j + 3);
            int gA = __shfl_sync(0xFFFFFFFFu, ag, j);
            int gB = __shfl_sync(0xFFFFFFFFu, ag, j + 1);
            int gC = __shfl_sync(0xFFFFFFFFu, ag, j + 2);
            int gD = __shfl_sync(0xFFFFFFFFu, ag, j + 3);
            float2 v0 = __half22float2(g_hn[(size_t)s0 * 32 + lane]);
            float2 v1 = __half22float2(g_hn[(size_t)s1 * 32 + lane]);
            float2 v2 = __half22float2(g_hn[(size_t)s2 * 32 + lane]);
            float2 v3 = __half22float2(g_hn[(size_t)s3 * 32 + lane]);
            acc(a0, v0); if (gA >= 1) acc(a1, v0); if (gA >= 2) acc(a2, v0);
            acc(a0, v1); if (gB >= 1) acc(a1, v1); if (gB >= 2) acc(a2, v1);
            acc(a0, v2); if (gC >= 1) acc(a1, v2); if (gC >= 2) acc(a2, v2);
            acc(a0, v3); if (gD >= 1) acc(a1, v3); if (gD >= 2) acc(a2, v3);
        }
        for (; j < cnt; j++) {
            int s  = __shfl_sync(0xFFFFFFFFu, idx, j);
            int sa = __shfl_sync(0xFFFFFFFFu, ag,  j);
            float2 v = __half22float2(g_hn[(size_t)s * 32 + lane]);
            acc(a0, v); if (sa >= 1) acc(a1, v); if (sa >= 2) acc(a2, v);
        }
    }

    float2 r0 = ln_relu(a0), r1 = ln_relu(a1), r2 = ln_relu(a2);
    __half2* hb = g_h + (size_t)n * 96;
    hb[lane]      = __float22half2_rn(r0);
    hb[32 + lane] = __float22half2_rn(r1);
    hb[64 + lane] = __float22half2_rn(r2);

    float* ob = out + (size_t)n * OUT_COLS + 64;
    reinterpret_cast<float2*>(ob)[lane] = r0;
    reinterpret_cast<float2*>(ob + 192)[lane] =
        make_float2(r0.x - 0.5f * (r1.x + r2.x), r0.y - 0.5f * (r1.y + r2.y));
}

// ---------- layer 2: gather 3-window h(fp16) -> sums -> LN+ReLU -> final outputs ----------
__global__ __launch_bounds__(256) void layer2_kernel(float* __restrict__ out)
{
    int n    = (blockIdx.x * blockDim.x + threadIdx.x) >> 5;
    int lane = threadIdx.x & 31;
    if (n >= N_NODES) return;

    int beg = g_indptr[n], end = g_indptr[n + 1];
    float2 a0 = make_float2(0.f, 0.f), a1 = a0, a2 = a0;

    for (int base = beg; base < end; base += 32) {
        int cnt = min(32, end - base);
        int idx = (lane < cnt) ? g_csr[base + lane] : 0;
        int j = 0;
        for (; j + 2 <= cnt; j += 2) {
            int s0 = __shfl_sync(0xFFFFFFFFu, idx, j);
            int s1 = __shfl_sync(0xFFFFFFFFu, idx, j + 1);
            const __half2* hA = g_h + (size_t)s0 * 96;
            const __half2* hB = g_h + (size_t)s1 * 96;
            float2 a0v = __half22float2(hA[lane]);
            float2 a1v = __half22float2(hA[32 + lane]);
            float2 a2v = __half22float2(hA[64 + lane]);
            float2 b0v = __half22float2(hB[lane]);
            float2 b1v = __half22float2(hB[32 + lane]);
            float2 b2v = __half22float2(hB[64 + lane]);
            acc(a0, a0v); acc(a1, a1v); acc(a2, a2v);
            acc(a0, b0v); acc(a1, b1v); acc(a2, b2v);
        }
        for (; j < cnt; j++) {
            int s = __shfl_sync(0xFFFFFFFFu, idx, j);
            const __half2* hs = g_h + (size_t)s * 96;
            acc(a0, __half22float2(hs[lane]));
            acc(a1, __half22float2(hs[32 + lane]));
            acc(a2, __half22float2(hs[64 + lane]));
        }
    }

    float2 r0 = ln_relu(a0), r1 = ln_relu(a1), r2 = ln_relu(a2);
    float* ob = out + (size_t)n * OUT_COLS + 128;
    reinterpret_cast<float2*>(ob)[lane] = r0;
    reinterpret_cast<float2*>(ob + 192)[lane] =
        make_float2(r0.x - 0.5f * (r1.x + r2.x), r0.y - 0.5f * (r1.y + r2.y));
}

extern "C" void kernel_launch(void* const* d_in, const int* in_sizes, int n_in,
                              void* d_out, int out_size)
{
    const float* feat = (const float*)d_in[0];
    const int*   age  = (const int*)  d_in[1];
    const int*   src  = (const int*)  d_in[2];
    const int*   dst  = (const int*)  d_in[3];
    float* out = (float*)d_out;

    const int nodeWarpBlocks = (N_NODES * 32 + 255) / 256;  // 12500
    const int edgeBlocks     = (N_EDGES + 255) / 256;       // 4688

    init_kernel<<<nodeWarpBlocks, 256>>>(feat, age, out);
    hist_kernel<<<edgeBlocks, 256>>>(dst);
    scanA_kernel<<<NSCAN, SCAN_BLK>>>();
    scanB_kernel<<<1, 256>>>();
    scanC_kernel<<<NSCAN, SCAN_BLK>>>();
    scatter_kernel<<<edgeBlocks, 256>>>(src, dst);
    layer1_kernel<<<nodeWarpBlocks, 256>>>(age, out);
    layer2_kernel<<<nodeWarpBlocks, 256>>>(out);
}